// round 7
// baseline (speedup 1.0000x reference)
#include <cuda_runtime.h>
#include <cuda_fp16.h>
#include <cstdint>

// ---------------- problem constants -----------------------------------------
#define MROWS 8192      // B*C = 32*256
#define VIN   6890
#define VOUT  1723
#define KPAD  6912      // 108 * 64
#define NPAD  1792      // 14 * 128
#define NSPLIT 2
#define KSPLIT (KPAD / NSPLIT)   // 3456

// fp16 scratch + fp32 split-K partials (device globals; no runtime allocation)
__device__ __align__(16) __half g_Xh[(size_t)MROWS * KPAD];            // ~113 MB
__device__ __align__(16) __half g_Mh[(size_t)NPAD  * KPAD];            // ~25 MB
__device__ __align__(16) float  g_P[(size_t)NSPLIT * MROWS * NPAD];    // ~117 MB

// ---------------- vectorized fp32 -> fp16 conversion ------------------------
__global__ void convert_x_v(const float* __restrict__ x) {
    int k8 = blockIdx.x * blockDim.x + threadIdx.x;
    if (k8 >= KPAD / 8) return;
    int row = blockIdx.y;
    int k = k8 * 8;
    const float* src = x + (size_t)row * VIN + k;
    __align__(16) __half h[8];
    if (k + 8 <= VIN) {
        #pragma unroll
        for (int j = 0; j < 4; ++j) {
            float2 f = *reinterpret_cast<const float2*>(src + 2 * j);
            h[2 * j]     = __float2half(f.x);
            h[2 * j + 1] = __float2half(f.y);
        }
    } else {
        #pragma unroll
        for (int j = 0; j < 8; ++j)
            h[j] = (k + j < VIN) ? __float2half(src[j]) : __float2half(0.0f);
    }
    *reinterpret_cast<uint4*>(&g_Xh[(size_t)row * KPAD + k]) =
        *reinterpret_cast<const uint4*>(h);
}

__global__ void convert_m_v(const float* __restrict__ m) {
    int k8 = blockIdx.x * blockDim.x + threadIdx.x;
    if (k8 >= KPAD / 8) return;
    int row = blockIdx.y;
    int k = k8 * 8;
    __align__(16) __half h[8];
    if (row < VOUT) {
        const float* src = m + (size_t)row * VIN + k;
        if (k + 8 <= VIN) {
            #pragma unroll
            for (int j = 0; j < 4; ++j) {
                float2 f = *reinterpret_cast<const float2*>(src + 2 * j);
                h[2 * j]     = __float2half(f.x);
                h[2 * j + 1] = __float2half(f.y);
            }
        } else {
            #pragma unroll
            for (int j = 0; j < 8; ++j)
                h[j] = (k + j < VIN) ? __float2half(src[j]) : __float2half(0.0f);
        }
    } else {
        #pragma unroll
        for (int j = 0; j < 8; ++j) h[j] = __float2half(0.0f);
    }
    *reinterpret_cast<uint4*>(&g_Mh[(size_t)row * KPAD + k]) =
        *reinterpret_cast<const uint4*>(h);
}

// ---------------- PTX helpers -----------------------------------------------
__device__ __forceinline__ void cp_async16(void* smem, const void* gmem) {
    uint32_t s = (uint32_t)__cvta_generic_to_shared(smem);
    asm volatile("cp.async.cg.shared.global [%0], [%1], 16;\n" :: "r"(s), "l"(gmem));
}
__device__ __forceinline__ void cp_commit() {
    asm volatile("cp.async.commit_group;\n" ::: "memory");
}
template<int N> __device__ __forceinline__ void cp_wait() {
    asm volatile("cp.async.wait_group %0;\n" :: "n"(N) : "memory");
}
__device__ __forceinline__ void ldsm_x4(uint32_t& r0, uint32_t& r1, uint32_t& r2,
                                        uint32_t& r3, const void* p) {
    uint32_t s = (uint32_t)__cvta_generic_to_shared(p);
    asm volatile("ldmatrix.sync.aligned.m8n8.x4.shared.b16 {%0,%1,%2,%3}, [%4];\n"
                 : "=r"(r0), "=r"(r1), "=r"(r2), "=r"(r3) : "r"(s));
}
__device__ __forceinline__ void mma16816(float* c, const uint32_t* a, const uint32_t* b) {
    asm volatile("mma.sync.aligned.m16n8k16.row.col.f32.f16.f16.f32 "
                 "{%0,%1,%2,%3}, {%4,%5,%6,%7}, {%8,%9}, {%0,%1,%2,%3};\n"
                 : "+f"(c[0]), "+f"(c[1]), "+f"(c[2]), "+f"(c[3])
                 : "r"(a[0]), "r"(a[1]), "r"(a[2]), "r"(a[3]),
                   "r"(b[0]), "r"(b[1]));
}

// ---------------- split-K GEMM: P[s] = Xh[:, sK:(s+1)K] * Mh[:, sK:(s+1)K]^T -
// CTA tile 128x128, 4 warps (2x2), warp tile 64x64 -> 2x less LDSM traffic/MAC.
// 128 threads/CTA keeps regs <= 256 so 2 CTAs/SM co-reside.
#define BM 128
#define BN 128
#define KC 64
#define STAGES 3
#define NSTG_S (KSPLIT / KC)    // 54
#define LDS_K 72                // 64 + 8 pad halves: LDSM conflict-free
#define A_HALVES (BM * LDS_K)   // 9216
#define B_HALVES (BN * LDS_K)   // 9216
#define STG_HALVES (A_HALVES + B_HALVES)       // 18432
#define SMEM_BYTES (STAGES * STG_HALVES * 2)   // 110,592 B per CTA

__global__ __launch_bounds__(128, 2) void gemm_kernel() {
    extern __shared__ __align__(16) __half sm[];

    const int tid  = threadIdx.x;
    const int lane = tid & 31;
    const int warp = tid >> 5;    // 0..3
    const int wm   = warp & 1;    // m offset wm*64
    const int wn   = warp >> 1;   // n offset wn*64
    const int bn    = blockIdx.x * BN;
    const int split = blockIdx.y;
    const int bm    = blockIdx.z * BM;

    const __half* Ag = g_Xh + (size_t)bm * KPAD + (size_t)split * KSPLIT;
    const __half* Bg = g_Mh + (size_t)bn * KPAD + (size_t)split * KSPLIT;

    // stage fill: 1024 A-chunks + 1024 B-chunks (16B) over 128 threads
    auto loadStage = [&](int s) {
        __half* aS = sm + (s % STAGES) * STG_HALVES;
        __half* bS = aS + A_HALVES;
        const int kb = s * KC;
        #pragma unroll
        for (int i = 0; i < 8; ++i) {
            const int c = tid + i * 128;
            const int r = c >> 3, k16 = c & 7;
            cp_async16(aS + r * LDS_K + k16 * 8,
                       Ag + (size_t)r * KPAD + kb + k16 * 8);
        }
        #pragma unroll
        for (int i = 0; i < 8; ++i) {
            const int c = tid + i * 128;
            const int r = c >> 3, k16 = c & 7;
            cp_async16(bS + r * LDS_K + k16 * 8,
                       Bg + (size_t)r * KPAD + kb + k16 * 8);
        }
    };

    float acc[4][8][4];
    #pragma unroll
    for (int i = 0; i < 4; ++i)
        #pragma unroll
        for (int j = 0; j < 8; ++j)
            #pragma unroll
            for (int e = 0; e < 4; ++e) acc[i][j][e] = 0.0f;

    // prologue
    loadStage(0); cp_commit();
    loadStage(1); cp_commit();
    cp_wait<1>();
    __syncthreads();               // stage 0 resident

    for (int kt = 0; kt < NSTG_S; ++kt) {
        if (kt + 2 < NSTG_S) loadStage(kt + 2);
        cp_commit();

        const __half* aS = sm + (kt % STAGES) * STG_HALVES;
        const __half* bS = aS + A_HALVES;

        #pragma unroll
        for (int ks = 0; ks < 4; ++ks) {
            const int kstep = ks * 16;
            uint32_t a[4][4];
            uint32_t b[8][2];
            #pragma unroll
            for (int i = 0; i < 4; ++i) {
                const int row = wm * 64 + i * 16 + (lane & 15);
                const int col = kstep + (lane >> 4) * 8;
                ldsm_x4(a[i][0], a[i][1], a[i][2], a[i][3], aS + row * LDS_K + col);
            }
            #pragma unroll
            for (int j = 0; j < 4; ++j) {
                const int nrow = wn * 64 + j * 16 + (lane & 7) + ((lane >> 4) << 3);
                const int col  = kstep + (((lane >> 3) & 1) << 3);
                uint32_t t0, t1, t2, t3;
                ldsm_x4(t0, t1, t2, t3, bS + nrow * LDS_K + col);
                b[2 * j][0] = t0;     b[2 * j][1] = t1;
                b[2 * j + 1][0] = t2; b[2 * j + 1][1] = t3;
            }
            #pragma unroll
            for (int i = 0; i < 4; ++i)
                #pragma unroll
                for (int jn = 0; jn < 8; ++jn)
                    mma16816(acc[i][jn], a[i], b[jn]);
        }

        cp_wait<1>();
        __syncthreads();           // stage kt+1 resident; all warps done with kt
    }

    // epilogue: unguarded float2 stores into NPAD-stride partial buffer
    float* P = g_P + (size_t)split * MROWS * NPAD;
    const int g  = lane >> 2;
    const int tc = lane & 3;
    #pragma unroll
    for (int i = 0; i < 4; ++i) {
        #pragma unroll
        for (int jn = 0; jn < 8; ++jn) {
            const int row = bm + wm * 64 + i * 16 + g;
            const int col = bn + wn * 64 + jn * 8 + tc * 2;
            *reinterpret_cast<float2*>(&P[(size_t)row * NPAD + col]) =
                make_float2(acc[i][jn][0], acc[i][jn][1]);
            *reinterpret_cast<float2*>(&P[(size_t)(row + 8) * NPAD + col]) =
                make_float2(acc[i][jn][2], acc[i][jn][3]);
        }
    }
}

// ---------------- split-K reduction: out = P0 + P1 (VOUT-packed) -------------
__global__ void reduce_k(float* __restrict__ out) {
    const size_t idx = (size_t)blockIdx.x * blockDim.x + threadIdx.x;
    const size_t ngroups = (size_t)MROWS * (NPAD / 4);
    if (idx >= ngroups) return;
    const int row = (int)(idx / (NPAD / 4));
    const int col = (int)(idx % (NPAD / 4)) * 4;
    const size_t off = (size_t)row * NPAD + col;
    float4 a = *reinterpret_cast<const float4*>(&g_P[off]);
    float4 b = *reinterpret_cast<const float4*>(&g_P[(size_t)MROWS * NPAD + off]);
    float v[4] = {a.x + b.x, a.y + b.y, a.z + b.z, a.w + b.w};
    float* orow = out + (size_t)row * VOUT;
    #pragma unroll
    for (int j = 0; j < 4; ++j)
        if (col + j < VOUT) orow[col + j] = v[j];
}

// ---------------- entry ------------------------------------------------------
extern "C" void kernel_launch(void* const* d_in, const int* in_sizes, int n_in,
                              void* d_out, int out_size) {
    const float* x = (const float*)d_in[0];  // (32,256,6890) fp32
    const float* M = (const float*)d_in[1];  // (1723,6890) fp32
    float* out = (float*)d_out;              // (32,256,1723) fp32

    cudaFuncSetAttribute(gemm_kernel, cudaFuncAttributeMaxDynamicSharedMemorySize,
                         SMEM_BYTES);

    convert_x_v<<<dim3((KPAD / 8 + 127) / 128, MROWS), 128>>>(x);
    convert_m_v<<<dim3((KPAD / 8 + 127) / 128, NPAD),  128>>>(M);
    gemm_kernel<<<dim3(NPAD / BN, NSPLIT, MROWS / BM), 128, SMEM_BYTES>>>();
    const size_t ngroups = (size_t)MROWS * (NPAD / 4);
    reduce_k<<<(unsigned)((ngroups + 255) / 256), 256>>>(out);
}